// round 3
// baseline (speedup 1.0000x reference)
#include <cuda_runtime.h>

#define BATCH 2048
#define NTOK 64
#define DIM 512
#define HEADS 16
#define QKV 1536
#define MTOT (BATCH * NTOK)      // 131072 rows

// ---------------------------------------------------------------------------
// Scratch (static __device__ globals; no allocations allowed)
// ---------------------------------------------------------------------------
__device__ float g_qkv[MTOT * QKV];    // 805 MB: qkv = x @ w_qkv + b_qkv
__device__ float g_attn[MTOT * DIM];   // 268 MB: attention output (pre-proj)
__device__ float g_Kss[NTOK * NTOK];   // row-normalised gaussian * softmax scale

// ---------------------------------------------------------------------------
// TF32 helpers
// ---------------------------------------------------------------------------
__device__ __forceinline__ unsigned f2tf(float x) {
    unsigned r;
    asm("cvt.rna.tf32.f32 %0, %1;" : "=r"(r) : "f"(x));
    return r;
}
__device__ __forceinline__ float f2tf_f(float x) { return __uint_as_float(f2tf(x)); }

__device__ __forceinline__ void mma8(float c[4],
                                     unsigned a0, unsigned a1, unsigned a2, unsigned a3,
                                     unsigned b0, unsigned b1) {
    asm volatile(
        "mma.sync.aligned.m16n8k8.row.col.f32.tf32.tf32.f32 "
        "{%0,%1,%2,%3}, {%4,%5,%6,%7}, {%8,%9}, {%0,%1,%2,%3};\n"
        : "+f"(c[0]), "+f"(c[1]), "+f"(c[2]), "+f"(c[3])
        : "r"(a0), "r"(a1), "r"(a2), "r"(a3), "r"(b0), "r"(b1));
}

// ---------------------------------------------------------------------------
// Precompute Kss[i][j] = gaussian_kernel(8, 0.39)[i][j] * HEAD_DIM^-0.5
// (row-normalised). 64 threads, one row each.
// ---------------------------------------------------------------------------
__global__ void init_kss_kernel() {
    const int i = threadIdx.x;  // 0..63
    const float yi = (float)(i >> 3), xi = (float)(i & 7);
    const float inv2s2 = 1.0f / (2.0f * 0.39f * 0.39f);
    float row[64];
    float s = 0.f;
#pragma unroll
    for (int j = 0; j < 64; ++j) {
        float dy = yi - (float)(j >> 3);
        float dx = xi - (float)(j & 7);
        float e = __expf(-(dy * dy + dx * dx) * inv2s2);
        row[j] = e;
        s += e;
    }
    const float inv = 0.17677669529663688f / s;  // scale / rowsum
#pragma unroll
    for (int j = 0; j < 64; ++j) g_Kss[i * 64 + j] = row[j] * inv;
}

// ---------------------------------------------------------------------------
// TF32 GEMM: C[M, LDB] = A[M, 512] @ Bw[512, LDB] + bias
//   MODE 0: A = x (param),  C = g_qkv, LDB = 1536
//   MODE 1: A = g_attn,     C = out (param), LDB = 512
// CTA tile 128x128, K-tile 32, 256 threads (8 warps as 4m x 2n, warp = 32x64).
// ---------------------------------------------------------------------------
template <int MODE>
__global__ void __launch_bounds__(256) gemm_tf32_kernel(
    const float* __restrict__ Aext,
    const float* __restrict__ Bw,
    const float* __restrict__ bias,
    float* __restrict__ Cext) {
    constexpr int LDB = (MODE == 0) ? QKV : DIM;
    const float* __restrict__ A = (MODE == 0) ? Aext : (const float*)g_attn;
    float* __restrict__ C = (MODE == 0) ? (float*)g_qkv : Cext;

    __shared__ float As[128 * 36];   // 128 rows x 32 k, pad to 36
    __shared__ float Bs[32 * 136];   // 32 k x 128 n, pad to 136

    const int tid = threadIdx.x;
    const int lane = tid & 31;
    const int wid = tid >> 5;
    const int wm = wid >> 1;  // 0..3
    const int wn = wid & 1;   // 0..1
    const int g = lane >> 2;  // 0..7
    const int t = lane & 3;   // 0..3

    const int brow = blockIdx.y * 128;
    const int bcol = blockIdx.x * 128;

    const int rowA = tid >> 3;         // 0..31 (+32 per it)
    const int colA = (tid & 7) << 2;   // 0..28
    const int rowB = tid >> 5;         // 0..7  (+8 per it)
    const int colB = (tid & 31) << 2;  // 0..124

    float acc[2][8][4];
#pragma unroll
    for (int mt = 0; mt < 2; ++mt)
#pragma unroll
        for (int nt = 0; nt < 8; ++nt)
#pragma unroll
            for (int e = 0; e < 4; ++e) acc[mt][nt][e] = 0.f;

    float4 pa[4], pb[4];

    // prologue: load k-tile 0
#pragma unroll
    for (int it = 0; it < 4; ++it) {
        pa[it] = *(const float4*)(A + (size_t)(brow + rowA + it * 32) * 512 + colA);
        pb[it] = *(const float4*)(Bw + (size_t)(rowB + it * 8) * LDB + bcol + colB);
    }
#pragma unroll
    for (int it = 0; it < 4; ++it) {
        const int r = rowA + it * 32;
        As[r * 36 + colA + 0] = f2tf_f(pa[it].x);
        As[r * 36 + colA + 1] = f2tf_f(pa[it].y);
        As[r * 36 + colA + 2] = f2tf_f(pa[it].z);
        As[r * 36 + colA + 3] = f2tf_f(pa[it].w);
        const int rb = rowB + it * 8;
        Bs[rb * 136 + colB + 0] = f2tf_f(pb[it].x);
        Bs[rb * 136 + colB + 1] = f2tf_f(pb[it].y);
        Bs[rb * 136 + colB + 2] = f2tf_f(pb[it].z);
        Bs[rb * 136 + colB + 3] = f2tf_f(pb[it].w);
    }
    __syncthreads();

    for (int kt = 0; kt < 16; ++kt) {
        if (kt < 15) {
#pragma unroll
            for (int it = 0; it < 4; ++it) {
                pa[it] = *(const float4*)(A + (size_t)(brow + rowA + it * 32) * 512 +
                                          (kt + 1) * 32 + colA);
                pb[it] = *(const float4*)(Bw + (size_t)((kt + 1) * 32 + rowB + it * 8) * LDB +
                                          bcol + colB);
            }
        }
#pragma unroll
        for (int kk = 0; kk < 4; ++kk) {
            const int k0 = kk * 8;
            unsigned a[2][4];
#pragma unroll
            for (int mt = 0; mt < 2; ++mt) {
                const int r = wm * 32 + mt * 16 + g;
                a[mt][0] = __float_as_uint(As[r * 36 + k0 + t]);
                a[mt][1] = __float_as_uint(As[(r + 8) * 36 + k0 + t]);
                a[mt][2] = __float_as_uint(As[r * 36 + k0 + t + 4]);
                a[mt][3] = __float_as_uint(As[(r + 8) * 36 + k0 + t + 4]);
            }
            unsigned bb[8][2];
#pragma unroll
            for (int nt = 0; nt < 8; ++nt) {
                const int cn = wn * 64 + nt * 8 + g;
                bb[nt][0] = __float_as_uint(Bs[(k0 + t) * 136 + cn]);
                bb[nt][1] = __float_as_uint(Bs[(k0 + t + 4) * 136 + cn]);
            }
#pragma unroll
            for (int mt = 0; mt < 2; ++mt)
#pragma unroll
                for (int nt = 0; nt < 8; ++nt)
                    mma8(acc[mt][nt], a[mt][0], a[mt][1], a[mt][2], a[mt][3],
                         bb[nt][0], bb[nt][1]);
        }
        __syncthreads();
        if (kt < 15) {
#pragma unroll
            for (int it = 0; it < 4; ++it) {
                const int r = rowA + it * 32;
                As[r * 36 + colA + 0] = f2tf_f(pa[it].x);
                As[r * 36 + colA + 1] = f2tf_f(pa[it].y);
                As[r * 36 + colA + 2] = f2tf_f(pa[it].z);
                As[r * 36 + colA + 3] = f2tf_f(pa[it].w);
                const int rb = rowB + it * 8;
                Bs[rb * 136 + colB + 0] = f2tf_f(pb[it].x);
                Bs[rb * 136 + colB + 1] = f2tf_f(pb[it].y);
                Bs[rb * 136 + colB + 2] = f2tf_f(pb[it].z);
                Bs[rb * 136 + colB + 3] = f2tf_f(pb[it].w);
            }
            __syncthreads();
        }
    }

    // epilogue: bias + store
#pragma unroll
    for (int mt = 0; mt < 2; ++mt) {
        const int r0 = brow + wm * 32 + mt * 16 + g;
#pragma unroll
        for (int nt = 0; nt < 8; ++nt) {
            const int c0 = bcol + wn * 64 + nt * 8 + 2 * t;
            const float2 bv = *(const float2*)(bias + c0);
            float2 lo = make_float2(acc[mt][nt][0] + bv.x, acc[mt][nt][1] + bv.y);
            float2 hi = make_float2(acc[mt][nt][2] + bv.x, acc[mt][nt][3] + bv.y);
            *(float2*)(C + (size_t)r0 * LDB + c0) = lo;
            *(float2*)(C + (size_t)(r0 + 8) * LDB + c0) = hi;
        }
    }
}

// ---------------------------------------------------------------------------
// Attention kernel: one CTA per (b, h). 128 threads = 4 warps, each warp owns
// 16 query rows. S = (Q Kᵀ) * (scale*Kss), softmax rows, O = P V.
// All small GEMMs via tf32 mma.
// ---------------------------------------------------------------------------
__global__ void __launch_bounds__(128) attn_kernel() {
    __shared__ float qs[64 * 36];
    __shared__ float ksm[64 * 36];
    __shared__ float vs[64 * 40];
    __shared__ float ps[64 * 68];

    const int bid = blockIdx.x;
    const int b = bid >> 4;
    const int h = bid & 15;
    const int tid = threadIdx.x;
    const int lane = tid & 31;
    const int wid = tid >> 5;
    const int g = lane >> 2;
    const int t = lane & 3;

    const size_t rowbase = (size_t)b * 64;

    // ---- load Q, K, V tiles (64 x 32 each, fp32 -> tf32 in smem) ----
    {
        const int r0 = tid >> 3;          // 0..15 (+16 per it)
        const int c4 = (tid & 7) << 2;    // 0..28
#pragma unroll
        for (int it = 0; it < 4; ++it) {
            const int r = r0 + it * 16;
            const float* src = g_qkv + (rowbase + r) * QKV;
            float4 q4 = *(const float4*)(src + h * 32 + c4);
            float4 k4 = *(const float4*)(src + 512 + h * 32 + c4);
            float4 v4 = *(const float4*)(src + 1024 + h * 32 + c4);
            qs[r * 36 + c4 + 0] = f2tf_f(q4.x);
            qs[r * 36 + c4 + 1] = f2tf_f(q4.y);
            qs[r * 36 + c4 + 2] = f2tf_f(q4.z);
            qs[r * 36 + c4 + 3] = f2tf_f(q4.w);
            ksm[r * 36 + c4 + 0] = f2tf_f(k4.x);
            ksm[r * 36 + c4 + 1] = f2tf_f(k4.y);
            ksm[r * 36 + c4 + 2] = f2tf_f(k4.z);
            ksm[r * 36 + c4 + 3] = f2tf_f(k4.w);
            vs[r * 40 + c4 + 0] = f2tf_f(v4.x);
            vs[r * 40 + c4 + 1] = f2tf_f(v4.y);
            vs[r * 40 + c4 + 2] = f2tf_f(v4.z);
            vs[r * 40 + c4 + 3] = f2tf_f(v4.w);
        }
    }
    __syncthreads();

    const int m0 = wid * 16;

    // ---- S = Q Kᵀ (warp: 16 rows x 64 cols, K=32) ----
    float s[8][4];
#pragma unroll
    for (int nt = 0; nt < 8; ++nt)
#pragma unroll
        for (int e = 0; e < 4; ++e) s[nt][e] = 0.f;

#pragma unroll
    for (int kk = 0; kk < 4; ++kk) {
        const int k0 = kk * 8;
        const unsigned a0 = __float_as_uint(qs[(m0 + g) * 36 + k0 + t]);
        const unsigned a1 = __float_as_uint(qs[(m0 + g + 8) * 36 + k0 + t]);
        const unsigned a2 = __float_as_uint(qs[(m0 + g) * 36 + k0 + t + 4]);
        const unsigned a3 = __float_as_uint(qs[(m0 + g + 8) * 36 + k0 + t + 4]);
#pragma unroll
        for (int nt = 0; nt < 8; ++nt) {
            const unsigned b0 = __float_as_uint(ksm[(nt * 8 + g) * 36 + k0 + t]);
            const unsigned b1 = __float_as_uint(ksm[(nt * 8 + g) * 36 + k0 + t + 4]);
            mma8(s[nt], a0, a1, a2, a3, b0, b1);
        }
    }

    // ---- elementwise gaussian mask (includes softmax scale) ----
    const int iA = m0 + g;
    const int iB = m0 + g + 8;
    float mA = -1e30f, mB = -1e30f;
#pragma unroll
    for (int nt = 0; nt < 8; ++nt) {
        const int j0 = nt * 8 + 2 * t;
        const float2 kA = *(const float2*)(g_Kss + iA * 64 + j0);
        const float2 kB = *(const float2*)(g_Kss + iB * 64 + j0);
        s[nt][0] *= kA.x;
        s[nt][1] *= kA.y;
        s[nt][2] *= kB.x;
        s[nt][3] *= kB.y;
        mA = fmaxf(mA, fmaxf(s[nt][0], s[nt][1]));
        mB = fmaxf(mB, fmaxf(s[nt][2], s[nt][3]));
    }
    // row max across the 4 lanes of each quad
    mA = fmaxf(mA, __shfl_xor_sync(0xffffffffu, mA, 1));
    mA = fmaxf(mA, __shfl_xor_sync(0xffffffffu, mA, 2));
    mB = fmaxf(mB, __shfl_xor_sync(0xffffffffu, mB, 1));
    mB = fmaxf(mB, __shfl_xor_sync(0xffffffffu, mB, 2));

    float sA = 0.f, sB = 0.f;
#pragma unroll
    for (int nt = 0; nt < 8; ++nt) {
        s[nt][0] = __expf(s[nt][0] - mA);
        s[nt][1] = __expf(s[nt][1] - mA);
        s[nt][2] = __expf(s[nt][2] - mB);
        s[nt][3] = __expf(s[nt][3] - mB);
        sA += s[nt][0] + s[nt][1];
        sB += s[nt][2] + s[nt][3];
    }
    sA += __shfl_xor_sync(0xffffffffu, sA, 1);
    sA += __shfl_xor_sync(0xffffffffu, sA, 2);
    sB += __shfl_xor_sync(0xffffffffu, sB, 1);
    sB += __shfl_xor_sync(0xffffffffu, sB, 2);
    const float rA = 1.0f / sA;
    const float rB = 1.0f / sB;

    // ---- write P to warp-private smem (tf32) ----
#pragma unroll
    for (int nt = 0; nt < 8; ++nt) {
        const int j0 = nt * 8 + 2 * t;
        float2 pl = make_float2(f2tf_f(s[nt][0] * rA), f2tf_f(s[nt][1] * rA));
        float2 ph = make_float2(f2tf_f(s[nt][2] * rB), f2tf_f(s[nt][3] * rB));
        *(float2*)(&ps[iA * 68 + j0]) = pl;
        *(float2*)(&ps[iB * 68 + j0]) = ph;
    }
    __syncwarp();

    // ---- O = P V (warp: 16 rows x 32 cols, K=64) ----
    float o[4][4];
#pragma unroll
    for (int nt = 0; nt < 4; ++nt)
#pragma unroll
        for (int e = 0; e < 4; ++e) o[nt][e] = 0.f;

#pragma unroll
    for (int kk = 0; kk < 8; ++kk) {
        const int k0 = kk * 8;
        const unsigned a0 = __float_as_uint(ps[(m0 + g) * 68 + k0 + t]);
        const unsigned a1 = __float_as_uint(ps[(m0 + g + 8) * 68 + k0 + t]);
        const unsigned a2 = __float_as_uint(ps[(m0 + g) * 68 + k0 + t + 4]);
        const unsigned a3 = __float_as_uint(ps[(m0 + g + 8) * 68 + k0 + t + 4]);
#pragma unroll
        for (int nt = 0; nt < 4; ++nt) {
            const unsigned b0 = __float_as_uint(vs[(k0 + t) * 40 + nt * 8 + g]);
            const unsigned b1 = __float_as_uint(vs[(k0 + t + 4) * 40 + nt * 8 + g]);
            mma8(o[nt], a0, a1, a2, a3, b0, b1);
        }
    }

    // ---- store O into g_attn[b*64+row, h*32+col] ----
#pragma unroll
    for (int nt = 0; nt < 4; ++nt) {
        const int cc = h * 32 + nt * 8 + 2 * t;
        *(float2*)(g_attn + (rowbase + m0 + g) * 512 + cc) =
            make_float2(o[nt][0], o[nt][1]);
        *(float2*)(g_attn + (rowbase + m0 + g + 8) * 512 + cc) =
            make_float2(o[nt][2], o[nt][3]);
    }
}

// ---------------------------------------------------------------------------
// Launch
// ---------------------------------------------------------------------------
extern "C" void kernel_launch(void* const* d_in, const int* in_sizes, int n_in,
                              void* d_out, int out_size) {
    (void)in_sizes;
    (void)n_in;
    (void)out_size;
    const float* x = (const float*)d_in[0];
    const float* w_qkv = (const float*)d_in[1];
    const float* b_qkv = (const float*)d_in[2];
    const float* w_proj = (const float*)d_in[3];
    const float* b_proj = (const float*)d_in[4];
    float* out = (float*)d_out;

    init_kss_kernel<<<1, 64>>>();
    gemm_tf32_kernel<0><<<dim3(QKV / 128, MTOT / 128), 256>>>(x, w_qkv, b_qkv, nullptr);
    attn_kernel<<<BATCH * HEADS, 128>>>();
    gemm_tf32_kernel<1><<<dim3(DIM / 128, MTOT / 128), 256>>>(nullptr, w_proj, b_proj, out);
}

// round 5
// speedup vs baseline: 1.6427x; 1.6427x over previous
#include <cuda_runtime.h>
#include <cuda_fp16.h>
#include <cstdint>

#define BATCH 2048
#define NTOK 64
#define DIM 512
#define HEADS 16
#define QKV 1536
#define MTOT (BATCH * NTOK)      // 131072 rows

// ---------------------------------------------------------------------------
// Scratch (static __device__ globals; no allocations allowed)
// ---------------------------------------------------------------------------
__device__ __half g_xh[(size_t)MTOT * DIM];      // 134 MB: x in fp16
__device__ __half g_qkvh[(size_t)MTOT * QKV];    // 403 MB: qkv (fp16)
__device__ __half g_attnh[(size_t)MTOT * DIM];   // 134 MB: attention out (fp16)
__device__ __half g_wqkvth[QKV * DIM];           // w_qkv^T  [1536][512] fp16
__device__ __half g_wprojth[DIM * DIM];          // w_proj^T [512][512] fp16
__device__ float g_Kss[NTOK * NTOK];             // gaussian * softmax scale

// ---------------------------------------------------------------------------
// PTX helpers
// ---------------------------------------------------------------------------
__device__ __forceinline__ uint32_t smem_u32(const void* p) {
    uint32_t a;
    asm("{ .reg .u64 t; cvta.to.shared.u64 t, %1; cvt.u32.u64 %0, t; }"
        : "=r"(a) : "l"(p));
    return a;
}

__device__ __forceinline__ void cp16(uint32_t dst, const void* src) {
    asm volatile("cp.async.cg.shared.global [%0], [%1], 16;"
                 :: "r"(dst), "l"(src));
}
#define CP_COMMIT() asm volatile("cp.async.commit_group;")
#define CP_WAIT(N) asm volatile("cp.async.wait_group %0;" :: "n"(N))

#define LDSM_X4(R0, R1, R2, R3, ADDR) \
    asm volatile("ldmatrix.sync.aligned.m8n8.x4.shared.b16 {%0,%1,%2,%3}, [%4];" \
                 : "=r"(R0), "=r"(R1), "=r"(R2), "=r"(R3) : "r"(ADDR))
#define LDSM_X4_T(R0, R1, R2, R3, ADDR) \
    asm volatile("ldmatrix.sync.aligned.m8n8.x4.trans.shared.b16 {%0,%1,%2,%3}, [%4];" \
                 : "=r"(R0), "=r"(R1), "=r"(R2), "=r"(R3) : "r"(ADDR))

__device__ __forceinline__ void mma16816(float c[4], const uint32_t a[4],
                                         uint32_t b0, uint32_t b1) {
    asm volatile(
        "mma.sync.aligned.m16n8k16.row.col.f32.f16.f16.f32 "
        "{%0,%1,%2,%3}, {%4,%5,%6,%7}, {%8,%9}, {%0,%1,%2,%3};"
        : "+f"(c[0]), "+f"(c[1]), "+f"(c[2]), "+f"(c[3])
        : "r"(a[0]), "r"(a[1]), "r"(a[2]), "r"(a[3]), "r"(b0), "r"(b1));
}

// ---------------------------------------------------------------------------
// Kss precompute: row-normalised gaussian * HEAD_DIM^-0.5
// ---------------------------------------------------------------------------
__global__ void init_kss_kernel() {
    const int i = threadIdx.x;  // 0..63
    const float yi = (float)(i >> 3), xi = (float)(i & 7);
    const float inv2s2 = 1.0f / (2.0f * 0.39f * 0.39f);
    float row[64];
    float s = 0.f;
#pragma unroll
    for (int j = 0; j < 64; ++j) {
        float dy = yi - (float)(j >> 3);
        float dx = xi - (float)(j & 7);
        float e = __expf(-(dy * dy + dx * dx) * inv2s2);
        row[j] = e;
        s += e;
    }
    const float inv = 0.17677669529663688f / s;  // scale / rowsum
#pragma unroll
    for (int j = 0; j < 64; ++j) g_Kss[i * 64 + j] = row[j] * inv;
}

// ---------------------------------------------------------------------------
// x fp32 -> fp16
// ---------------------------------------------------------------------------
__global__ void cvt_x_kernel(const float* __restrict__ x) {
    const size_t i = ((size_t)blockIdx.x * 256 + threadIdx.x) * 8;
    float4 a = *(const float4*)(x + i);
    float4 b = *(const float4*)(x + i + 4);
    __half h[8];
    h[0] = __float2half_rn(a.x); h[1] = __float2half_rn(a.y);
    h[2] = __float2half_rn(a.z); h[3] = __float2half_rn(a.w);
    h[4] = __float2half_rn(b.x); h[5] = __float2half_rn(b.y);
    h[6] = __float2half_rn(b.z); h[7] = __float2half_rn(b.w);
    *(uint4*)(&g_xh[i]) = *(uint4*)h;
}

// ---------------------------------------------------------------------------
// Weight transpose + fp16 convert: dst[n][k] = h(src[k][n]); K = 512
// ---------------------------------------------------------------------------
template <int MODE>
__global__ void transpose_cvt_kernel(const float* __restrict__ src) {
    constexpr int N = (MODE == 0) ? QKV : DIM;
    __half* __restrict__ dst = (MODE == 0) ? (__half*)g_wqkvth : (__half*)g_wprojth;
    __shared__ float t[32][33];
    const int bx = blockIdx.x * 32;  // n
    const int by = blockIdx.y * 32;  // k
    const int x = threadIdx.x, y = threadIdx.y;  // 32 x 8
#pragma unroll
    for (int i = 0; i < 32; i += 8)
        t[y + i][x] = src[(size_t)(by + y + i) * N + bx + x];
    __syncthreads();
#pragma unroll
    for (int i = 0; i < 32; i += 8)
        dst[(size_t)(bx + y + i) * 512 + by + x] = __float2half_rn(t[x][y + i]);
}

// ---------------------------------------------------------------------------
// fp16 GEMM: C[M, N] = A[M, 512] @ Bt[N, 512]^T + bias
// CTA 128x128, 256 thr (8 warps 4m x 2n, warp 32x64), k-tile 64, cp.async
// double-buffered, ldmatrix fragments.
// MODE 0: A=g_xh,    C=g_qkvh (fp16), N=1536
// MODE 1: A=g_attnh, C=out (fp32),    N=512
// smem: buf0A@0, buf0B@18432, buf1A@36864, buf1B@55296 (each 128*144B)
// ---------------------------------------------------------------------------
#define GSM_TOTAL 73728

template <int MODE>
__global__ void __launch_bounds__(256, 2) gemm_h_kernel(
    const float* __restrict__ bias, float* __restrict__ CoutF) {
    constexpr int N = (MODE == 0) ? QKV : DIM;
    const __half* __restrict__ A = (MODE == 0) ? (const __half*)g_xh
                                               : (const __half*)g_attnh;
    const __half* __restrict__ Bt = (MODE == 0) ? (const __half*)g_wqkvth
                                                : (const __half*)g_wprojth;

    extern __shared__ char sm[];
    const uint32_t sb = smem_u32(sm);
    const int tid = threadIdx.x;
    const int lane = tid & 31;
    const int wid = tid >> 5;
    const int wm = wid >> 1;  // 0..3
    const int wn = wid & 1;   // 0..1

    const int brow = blockIdx.y * 128;
    const int bcol = blockIdx.x * 128;

    // loader: 8 lanes per 128B row chunk group
    const int lr = tid >> 3;       // 0..31
    const int lc = tid & 7;        // chunk
    const char* Abase = (const char*)(A + (size_t)(brow + lr) * 512) + lc * 16;
    const char* Bbase = (const char*)(Bt + (size_t)(bcol + lr) * 512) + lc * 16;
    const uint32_t sA[2] = {sb + 0, sb + 36864};
    const uint32_t sB[2] = {sb + 18432, sb + 55296};
    const uint32_t dstoff = (uint32_t)(lr * 144 + lc * 16);

    float c[2][8][4];
#pragma unroll
    for (int mt = 0; mt < 2; ++mt)
#pragma unroll
        for (int nt = 0; nt < 8; ++nt)
#pragma unroll
            for (int e = 0; e < 4; ++e) c[mt][nt][e] = 0.f;

#define LOAD_TILE(KT, BUF) do { \
    _Pragma("unroll") \
    for (int it = 0; it < 4; ++it) \
        cp16(sA[BUF] + dstoff + it * 32 * 144, Abase + (size_t)it * 32 * 1024 + (KT) * 128); \
    _Pragma("unroll") \
    for (int it = 0; it < 4; ++it) \
        cp16(sB[BUF] + dstoff + it * 32 * 144, Bbase + (size_t)it * 32 * 1024 + (KT) * 128); \
    CP_COMMIT(); \
} while (0)

    LOAD_TILE(0, 0);
    LOAD_TILE(1, 1);

#pragma unroll 1
    for (int kt = 0; kt < 8; ++kt) {
        const int buf = kt & 1;
        if (kt < 7) { CP_WAIT(1); } else { CP_WAIT(0); }
        __syncthreads();
#pragma unroll
        for (int kk = 0; kk < 4; ++kk) {
            uint32_t a[2][4], b[4][4];
#pragma unroll
            for (int mt = 0; mt < 2; ++mt) {
                const uint32_t addr = sA[buf] + (wm * 32 + mt * 16 + (lane & 15)) * 144 +
                                      kk * 32 + (lane >> 4) * 16;
                LDSM_X4(a[mt][0], a[mt][1], a[mt][2], a[mt][3], addr);
            }
#pragma unroll
            for (int nb = 0; nb < 4; ++nb) {
                const uint32_t addr = sB[buf] + (wn * 64 + nb * 16 + (lane & 15)) * 144 +
                                      kk * 32 + (lane >> 4) * 16;
                LDSM_X4(b[nb][0], b[nb][1], b[nb][2], b[nb][3], addr);
            }
#pragma unroll
            for (int mt = 0; mt < 2; ++mt)
#pragma unroll
                for (int nt = 0; nt < 8; ++nt)
                    mma16816(c[mt][nt], a[mt], b[nt >> 1][nt & 1],
                             b[nt >> 1][2 + (nt & 1)]);
        }
        __syncthreads();
        if (kt + 2 < 8) LOAD_TILE(kt + 2, buf);
    }

    // ---- epilogue: stage fp32 in smem (reuses buffers), coalesced store ----
    float* es = (float*)sm;  // 128 x 132
    const int g = lane >> 2, t4 = lane & 3;
#pragma unroll
    for (int mt = 0; mt < 2; ++mt) {
        const int r0 = wm * 32 + mt * 16 + g;
#pragma unroll
        for (int nt = 0; nt < 8; ++nt) {
            const int c0 = wn * 64 + nt * 8 + 2 * t4;
            *(float2*)&es[r0 * 132 + c0] = make_float2(c[mt][nt][0], c[mt][nt][1]);
            *(float2*)&es[(r0 + 8) * 132 + c0] = make_float2(c[mt][nt][2], c[mt][nt][3]);
        }
    }
    __syncthreads();

    if (MODE == 0) {
        const int cb = (tid & 15) * 8;
        float bb[8];
#pragma unroll
        for (int j = 0; j < 8; ++j) bb[j] = bias[bcol + cb + j];
#pragma unroll
        for (int it = 0; it < 8; ++it) {
            const int row = (tid >> 4) + it * 16;
            __half hv[8];
#pragma unroll
            for (int j = 0; j < 8; ++j)
                hv[j] = __float2half_rn(es[row * 132 + cb + j] + bb[j]);
            *(uint4*)(&g_qkvh[(size_t)(brow + row) * QKV + bcol + cb]) = *(uint4*)hv;
        }
    } else {
        const int cb = (tid & 31) * 4;
        const float4 bv = *(const float4*)(bias + bcol + cb);
#pragma unroll
        for (int it = 0; it < 16; ++it) {
            const int row = (tid >> 5) + it * 8;
            float4 o;
            o.x = es[row * 132 + cb + 0] + bv.x;
            o.y = es[row * 132 + cb + 1] + bv.y;
            o.z = es[row * 132 + cb + 2] + bv.z;
            o.w = es[row * 132 + cb + 3] + bv.w;
            *(float4*)(CoutF + (size_t)(brow + row) * DIM + bcol + cb) = o;
        }
    }
#undef LOAD_TILE
}

// ---------------------------------------------------------------------------
// Attention: one CTA per (b, h). 128 thr = 4 warps, warp owns 16 query rows.
// fp16 mma.m16n8k16 for S = Q K^T and O = P V; V consumed via ldmatrix.trans.
// ---------------------------------------------------------------------------
__global__ void __launch_bounds__(128) attn_kernel() {
    __shared__ __half qs[64 * 40];   // stride 40 halves = 80B
    __shared__ __half ks[64 * 40];
    __shared__ __half vsm[64 * 40];
    __shared__ __half ps[64 * 72];   // stride 72 halves = 144B

    const int bid = blockIdx.x;
    const int b = bid >> 4;
    const int h = bid & 15;
    const int tid = threadIdx.x;
    const int lane = tid & 31;
    const int wid = tid >> 5;
    const int g = lane >> 2;
    const int t = lane & 3;
    const size_t rowbase = (size_t)b * 64;

    const uint32_t qs_u = smem_u32(qs);
    const uint32_t ks_u = smem_u32(ks);
    const uint32_t vs_u = smem_u32(vsm);
    const uint32_t ps_u = smem_u32(ps);

    // ---- load Q, K, V (64 x 32 fp16 each) ----
#pragma unroll
    for (int it = 0; it < 2; ++it) {
        const int idx = tid + it * 128;
        const int row = idx >> 2;
        const int ch = idx & 3;
        const char* src = (const char*)(g_qkvh + (rowbase + row) * QKV + h * 32) + ch * 16;
        *(uint4*)((char*)qs + row * 80 + ch * 16) = *(const uint4*)(src);
        *(uint4*)((char*)ks + row * 80 + ch * 16) = *(const uint4*)(src + 512 * 2);
        *(uint4*)((char*)vsm + row * 80 + ch * 16) = *(const uint4*)(src + 1024 * 2);
    }
    __syncthreads();

    const int m0 = wid * 16;

    // ---- S = Q K^T : warp 16 x 64, K=32 ----
    float s[8][4];
#pragma unroll
    for (int nt = 0; nt < 8; ++nt)
#pragma unroll
        for (int e = 0; e < 4; ++e) s[nt][e] = 0.f;

#pragma unroll
    for (int kk = 0; kk < 2; ++kk) {
        uint32_t a[4];
        LDSM_X4(a[0], a[1], a[2], a[3],
                qs_u + (m0 + (lane & 15)) * 80 + kk * 32 + (lane >> 4) * 16);
#pragma unroll
        for (int nb = 0; nb < 4; ++nb) {
            uint32_t bb[4];
            LDSM_X4(bb[0], bb[1], bb[2], bb[3],
                    ks_u + (nb * 16 + (lane & 15)) * 80 + kk * 32 + (lane >> 4) * 16);
            mma16816(s[nb * 2], a, bb[0], bb[2]);
            mma16816(s[nb * 2 + 1], a, bb[1], bb[3]);
        }
    }

    // ---- gaussian mask (includes scale) + softmax ----
    const int iA = m0 + g;
    const int iB = m0 + g + 8;
    float mA = -1e30f, mB = -1e30f;
#pragma unroll
    for (int nt = 0; nt < 8; ++nt) {
        const int j0 = nt * 8 + 2 * t;
        const float2 kA = *(const float2*)(g_Kss + iA * 64 + j0);
        const float2 kB = *(const float2*)(g_Kss + iB * 64 + j0);
        s[nt][0] *= kA.x;
        s[nt][1] *= kA.y;
        s[nt][2] *= kB.x;
        s[nt][3] *= kB.y;
        mA = fmaxf(mA, fmaxf(s[nt][0], s[nt][1]));
        mB = fmaxf(mB, fmaxf(s[nt][2], s[nt][3]));
    }
    mA = fmaxf(mA, __shfl_xor_sync(0xffffffffu, mA, 1));
    mA = fmaxf(mA, __shfl_xor_sync(0xffffffffu, mA, 2));
    mB = fmaxf(mB, __shfl_xor_sync(0xffffffffu, mB, 1));
    mB = fmaxf(mB, __shfl_xor_sync(0xffffffffu, mB, 2));

    float sA = 0.f, sB = 0.f;
#pragma unroll
    for (int nt = 0; nt < 8; ++nt) {
        s[nt][0] = __expf(s[nt][0] - mA);
        s[nt][1] = __expf(s[nt][1] - mA);
        s[nt][2] = __expf(s[nt][2] - mB);
        s[nt][3] = __expf(s[nt][3] - mB);
        sA += s[nt][0] + s[nt][1];
        sB += s[nt][2] + s[nt][3];
    }
    sA += __shfl_xor_sync(0xffffffffu, sA, 1);
    sA += __shfl_xor_sync(0xffffffffu, sA, 2);
    sB += __shfl_xor_sync(0xffffffffu, sB, 1);
    sB += __shfl_xor_sync(0xffffffffu, sB, 2);
    const float rA = 1.0f / sA;
    const float rB = 1.0f / sB;

    // ---- P -> smem fp16 (warp-private rows) ----
#pragma unroll
    for (int nt = 0; nt < 8; ++nt) {
        const int j0 = nt * 8 + 2 * t;
        *(half2*)((char*)ps + iA * 144 + j0 * 2) =
            __floats2half2_rn(s[nt][0] * rA, s[nt][1] * rA);
        *(half2*)((char*)ps + iB * 144 + j0 * 2) =
            __floats2half2_rn(s[nt][2] * rB, s[nt][3] * rB);
    }
    __syncwarp();

    // ---- O = P V : warp 16 x 32, K=64 ----
    float o[4][4];
#pragma unroll
    for (int nt = 0; nt < 4; ++nt)
#pragma unroll
        for (int e = 0; e < 4; ++e) o[nt][e] = 0.f;

#pragma unroll
    for (int kk = 0; kk < 4; ++kk) {
        uint32_t a[4];
        LDSM_X4(a[0], a[1], a[2], a[3],
                ps_u + (m0 + (lane & 15)) * 144 + kk * 32 + (lane >> 4) * 16);
#pragma unroll
        for (int nb = 0; nb < 2; ++nb) {
            uint32_t bb[4];
            LDSM_X4_T(bb[0], bb[1], bb[2], bb[3],
                      vs_u + (kk * 16 + (lane & 15)) * 80 + nb * 32 + (lane >> 4) * 16);
            mma16816(o[nb * 2], a, bb[0], bb[1]);
            mma16816(o[nb * 2 + 1], a, bb[2], bb[3]);
        }
    }

    // ---- store O fp16 into g_attnh[b*64+row][h*32+col] ----
#pragma unroll
    for (int nt = 0; nt < 4; ++nt) {
        const int cc = h * 32 + nt * 8 + 2 * t;
        *(half2*)(g_attnh + (rowbase + iA) * 512 + cc) =
            __floats2half2_rn(o[nt][0], o[nt][1]);
        *(half2*)(g_attnh + (rowbase + iB) * 512 + cc) =
            __floats2half2_rn(o[nt][2], o[nt][3]);
    }
}

// ---------------------------------------------------------------------------
// Launch
// ---------------------------------------------------------------------------
extern "C" void kernel_launch(void* const* d_in, const int* in_sizes, int n_in,
                              void* d_out, int out_size) {
    (void)in_sizes;
    (void)n_in;
    (void)out_size;
    const float* x = (const float*)d_in[0];
    const float* w_qkv = (const float*)d_in[1];
    const float* b_qkv = (const float*)d_in[2];
    const float* w_proj = (const float*)d_in[3];
    const float* b_proj = (const float*)d_in[4];
    float* out = (float*)d_out;

    cudaFuncSetAttribute(gemm_h_kernel<0>,
                         cudaFuncAttributeMaxDynamicSharedMemorySize, GSM_TOTAL);
    cudaFuncSetAttribute(gemm_h_kernel<1>,
                         cudaFuncAttributeMaxDynamicSharedMemorySize, GSM_TOTAL);

    init_kss_kernel<<<1, 64>>>();
    cvt_x_kernel<<<MTOT * DIM / 8 / 256, 256>>>(x);
    transpose_cvt_kernel<0><<<dim3(QKV / 32, DIM / 32), dim3(32, 8)>>>(w_qkv);
    transpose_cvt_kernel<1><<<dim3(DIM / 32, DIM / 32), dim3(32, 8)>>>(w_proj);
    gemm_h_kernel<0><<<dim3(QKV / 128, MTOT / 128), 256, GSM_TOTAL>>>(b_qkv, nullptr);
    attn_kernel<<<BATCH * HEADS, 128>>>();
    gemm_h_kernel<1><<<dim3(DIM / 128, MTOT / 128), 256, GSM_TOTAL>>>(b_proj, out);
}